// round 2
// baseline (speedup 1.0000x reference)
#include <cuda_runtime.h>

#define S_LEN   4096
#define DMODEL  1024
#define NHEADS  16
#define DK      64

// Scratch (allocation-free rule: __device__ globals)
__device__ float g_q [S_LEN * DMODEL];
__device__ float g_k [S_LEN * DMODEL];
__device__ float g_v [S_LEN * DMODEL];
__device__ float g_ao[S_LEN * DMODEL];

// ---------------------------------------------------------------------------
// NT GEMM: C[M,N] = A[M,K] * B[N,K]^T   (both A and B are K-major row dots)
// 128x128 tile, BK=8, 256 threads, 8x8 register micro-tile.
// ---------------------------------------------------------------------------
#define BM 128
#define BN 128
#define BKS 8

__global__ void __launch_bounds__(256) gemm_nt(const float* __restrict__ A,
                                               const float* __restrict__ B,
                                               float* __restrict__ C,
                                               int M, int N, int K) {
    __shared__ float As[BKS][BM];
    __shared__ float Bs[BKS][BN];
    const int bm  = blockIdx.y * BM;
    const int bn  = blockIdx.x * BN;
    const int tid = threadIdx.x;
    const int tx  = tid & 15;       // 0..15 -> n micro-tile
    const int ty  = tid >> 4;       // 0..15 -> m micro-tile
    const int lr  = tid >> 1;       // 0..127 row for loads
    const int lc4 = (tid & 1) * 4;  // 0 or 4 (k offset)

    float acc[8][8];
#pragma unroll
    for (int i = 0; i < 8; i++)
#pragma unroll
        for (int j = 0; j < 8; j++) acc[i][j] = 0.f;

    for (int k0 = 0; k0 < K; k0 += BKS) {
        float4 a4 = *(const float4*)(A + (size_t)(bm + lr) * K + k0 + lc4);
        float4 b4 = *(const float4*)(B + (size_t)(bn + lr) * K + k0 + lc4);
        As[lc4 + 0][lr] = a4.x; As[lc4 + 1][lr] = a4.y;
        As[lc4 + 2][lr] = a4.z; As[lc4 + 3][lr] = a4.w;
        Bs[lc4 + 0][lr] = b4.x; Bs[lc4 + 1][lr] = b4.y;
        Bs[lc4 + 2][lr] = b4.z; Bs[lc4 + 3][lr] = b4.w;
        __syncthreads();
#pragma unroll
        for (int kk = 0; kk < BKS; kk++) {
            float ar[8], br[8];
            *(float4*)&ar[0] = *(const float4*)&As[kk][ty * 8];
            *(float4*)&ar[4] = *(const float4*)&As[kk][ty * 8 + 4];
            *(float4*)&br[0] = *(const float4*)&Bs[kk][tx * 8];
            *(float4*)&br[4] = *(const float4*)&Bs[kk][tx * 8 + 4];
#pragma unroll
            for (int i = 0; i < 8; i++)
#pragma unroll
                for (int j = 0; j < 8; j++) acc[i][j] += ar[i] * br[j];
        }
        __syncthreads();
    }
#pragma unroll
    for (int i = 0; i < 8; i++) {
        float* cp = C + (size_t)(bm + ty * 8 + i) * N + bn + tx * 8;
        *(float4*)cp       = make_float4(acc[i][0], acc[i][1], acc[i][2], acc[i][3]);
        *(float4*)(cp + 4) = make_float4(acc[i][4], acc[i][5], acc[i][6], acc[i][7]);
    }
}

// ---------------------------------------------------------------------------
// Flash attention: grid (S/64, H), 256 threads.
// Block = 64 queries x all 4096 keys in 64-key tiles, online softmax.
// Thread (ty,tx) in 16x16 grid owns 4 q-rows x 4 cols.
// SMEM: Qs (Q^T, scaled) + KP (K^T for QK^T, then P[q][t]) + Vs = 48KB exactly.
// ---------------------------------------------------------------------------
__global__ void __launch_bounds__(256) attn_fa(const float* __restrict__ Qg,
                                               const float* __restrict__ Kg,
                                               const float* __restrict__ Vg,
                                               float* __restrict__ Og) {
    __shared__ float Qs[DK][64];   // Qs[d][q]
    __shared__ float KP[DK][64];   // phase A: K^T[d][t]; phase B/C: P[q][t]
    __shared__ float Vs[64][DK];   // Vs[t][d]

    const int h   = blockIdx.y;
    const int q0  = blockIdx.x * 64;
    const int tid = threadIdx.x;
    const int tx  = tid & 15;
    const int ty  = tid >> 4;
    const float scale = 0.125f;    // 1/sqrt(64)

    // Load Q tile transposed + pre-scaled.
    // Index mapping r = i & 63 makes the transposed STS lane-consecutive in r
    // -> conflict-free shared stores (global side is strided but L2-cached).
    for (int i = tid; i < 64 * DK / 4; i += 256) {
        int r  = i & 63;
        int c4 = (i >> 6) * 4;
        float4 t4 = *(const float4*)(Qg + (size_t)(q0 + r) * DMODEL + h * DK + c4);
        Qs[c4 + 0][r] = t4.x * scale; Qs[c4 + 1][r] = t4.y * scale;
        Qs[c4 + 2][r] = t4.z * scale; Qs[c4 + 3][r] = t4.w * scale;
    }

    float m_i[4], l_i[4], o[4][4];
#pragma unroll
    for (int i = 0; i < 4; i++) {
        m_i[i] = -1e30f; l_i[i] = 0.f;
#pragma unroll
        for (int j = 0; j < 4; j++) o[i][j] = 0.f;
    }

    for (int t0 = 0; t0 < S_LEN; t0 += 64) {
        __syncthreads();  // prev-iter P/Vs reads done before overwrite
        // K tile, transposed store (same conflict-free mapping as Q)
        for (int i = tid; i < 64 * DK / 4; i += 256) {
            int r  = i & 63;
            int c4 = (i >> 6) * 4;
            float4 t4 = *(const float4*)(Kg + (size_t)(t0 + r) * DMODEL + h * DK + c4);
            KP[c4 + 0][r] = t4.x; KP[c4 + 1][r] = t4.y;
            KP[c4 + 2][r] = t4.z; KP[c4 + 3][r] = t4.w;
        }
        // V tile, natural layout, coalesced global + conflict-free STS.128
        for (int i = tid; i < 64 * DK / 4; i += 256) {
            int r  = i >> 4;
            int c4 = (i & 15) * 4;
            float4 t4 = *(const float4*)(Vg + (size_t)(t0 + r) * DMODEL + h * DK + c4);
            *(float4*)&Vs[r][c4] = t4;
        }
        __syncthreads();

        // ---- Phase A: S = (Q*scale) K^T, 4x4 per thread ----
        float s[4][4];
#pragma unroll
        for (int i = 0; i < 4; i++)
#pragma unroll
            for (int j = 0; j < 4; j++) s[i][j] = 0.f;
#pragma unroll 8
        for (int d = 0; d < DK; d++) {
            float qa[4], kb[4];
            *(float4*)qa = *(const float4*)&Qs[d][ty * 4];
            *(float4*)kb = *(const float4*)&KP[d][tx * 4];
#pragma unroll
            for (int i = 0; i < 4; i++)
#pragma unroll
                for (int j = 0; j < 4; j++) s[i][j] += qa[i] * kb[j];
        }
        __syncthreads();  // all threads done reading KP as K^T

        // ---- Phase B: online softmax ----
        // Row reductions across the 16 tx threads of each q row; lane = (ty&1)*16+tx,
        // so xor-shuffles with offset<16 stay inside the row group.
        float mt[4];
#pragma unroll
        for (int i = 0; i < 4; i++)
            mt[i] = fmaxf(fmaxf(s[i][0], s[i][1]), fmaxf(s[i][2], s[i][3]));
#pragma unroll
        for (int off = 1; off < 16; off <<= 1)
#pragma unroll
            for (int i = 0; i < 4; i++)
                mt[i] = fmaxf(mt[i], __shfl_xor_sync(0xffffffffu, mt[i], off));

        float corr[4];
#pragma unroll
        for (int i = 0; i < 4; i++) {
            float mn = fmaxf(m_i[i], mt[i]);
            corr[i]  = __expf(m_i[i] - mn);
            m_i[i]   = mn;
        }
        float rs[4];
#pragma unroll
        for (int i = 0; i < 4; i++) {
            rs[i] = 0.f;
#pragma unroll
            for (int j = 0; j < 4; j++) {
                float p = __expf(s[i][j] - m_i[i]);
                KP[ty * 4 + i][tx * 4 + j] = p;   // write P over K^T
                rs[i] += p;
            }
        }
#pragma unroll
        for (int off = 1; off < 16; off <<= 1)
#pragma unroll
            for (int i = 0; i < 4; i++)
                rs[i] += __shfl_xor_sync(0xffffffffu, rs[i], off);
#pragma unroll
        for (int i = 0; i < 4; i++) {
            l_i[i] = l_i[i] * corr[i] + rs[i];
#pragma unroll
            for (int j = 0; j < 4; j++) o[i][j] *= corr[i];
        }
        __syncthreads();  // P visible to all

        // ---- Phase C: O += P V ----
#pragma unroll 8
        for (int kk = 0; kk < 64; kk++) {
            float pv[4], vv[4];
#pragma unroll
            for (int i = 0; i < 4; i++) pv[i] = KP[ty * 4 + i][kk];  // broadcast
            *(float4*)vv = *(const float4*)&Vs[kk][tx * 4];
#pragma unroll
            for (int i = 0; i < 4; i++)
#pragma unroll
                for (int j = 0; j < 4; j++) o[i][j] += pv[i] * vv[j];
        }
    }

    // Normalize + write
#pragma unroll
    for (int i = 0; i < 4; i++) {
        float inv = 1.f / l_i[i];
        float* op = Og + (size_t)(q0 + ty * 4 + i) * DMODEL + h * DK + tx * 4;
        *(float4*)op = make_float4(o[i][0] * inv, o[i][1] * inv,
                                   o[i][2] * inv, o[i][3] * inv);
    }
}

// ---------------------------------------------------------------------------
extern "C" void kernel_launch(void* const* d_in, const int* in_sizes, int n_in,
                              void* d_out, int out_size) {
    const float* x  = (const float*)d_in[0];
    const float* Wq = (const float*)d_in[1];
    const float* Wk = (const float*)d_in[2];
    const float* Wv = (const float*)d_in[3];
    const float* Wo = (const float*)d_in[4];
    float* out = (float*)d_out;

    float *q, *k, *v, *ao;
    cudaGetSymbolAddress((void**)&q,  g_q);
    cudaGetSymbolAddress((void**)&k,  g_k);
    cudaGetSymbolAddress((void**)&v,  g_v);
    cudaGetSymbolAddress((void**)&ao, g_ao);

    dim3 gg(DMODEL / BN, S_LEN / BM);  // (8, 32)
    gemm_nt<<<gg, 256>>>(x, Wq, q, S_LEN, DMODEL, DMODEL);
    gemm_nt<<<gg, 256>>>(x, Wk, k, S_LEN, DMODEL, DMODEL);
    gemm_nt<<<gg, 256>>>(x, Wv, v, S_LEN, DMODEL, DMODEL);

    attn_fa<<<dim3(S_LEN / 64, NHEADS), 256>>>(q, k, v, ao);

    gemm_nt<<<gg, 256>>>(ao, Wo, out, S_LEN, DMODEL, DMODEL);
}

// round 3
// speedup vs baseline: 2.9709x; 2.9709x over previous
#include <cuda_runtime.h>
#include <cstdint>

#define S_LEN   4096
#define DMODEL  1024
#define NHEADS  16
#define DK      64

// Scratch (allocation-free rule: __device__ globals)
__device__ float g_q [S_LEN * DMODEL];
__device__ float g_k [S_LEN * DMODEL];
__device__ float g_v [S_LEN * DMODEL];
__device__ float g_ao[S_LEN * DMODEL];

// ---------------------------------------------------------------------------
// tf32 helpers
// ---------------------------------------------------------------------------
__device__ __forceinline__ float f2tf(float f) {
    uint32_t r;
    asm("cvt.rna.tf32.f32 %0, %1;" : "=r"(r) : "f"(f));
    return __uint_as_float(r);
}

// D += A(16x8) * B(8x8), tf32 inputs, fp32 accum
__device__ __forceinline__ void mma8(float* d, const uint32_t* a, const uint32_t* b) {
    asm volatile(
        "mma.sync.aligned.m16n8k8.row.col.f32.tf32.tf32.f32 "
        "{%0,%1,%2,%3}, {%4,%5,%6,%7}, {%8,%9}, {%0,%1,%2,%3};"
        : "+f"(d[0]), "+f"(d[1]), "+f"(d[2]), "+f"(d[3])
        : "r"(a[0]), "r"(a[1]), "r"(a[2]), "r"(a[3]), "r"(b[0]), "r"(b[1]));
}

// ---------------------------------------------------------------------------
// NT GEMM (tf32 tensor cores): C[M,N] = A[M,K] * B[N,K]^T
// Block 128x128x32, 8 warps as 2(m) x 4(n), warp tile 64x32.
// ---------------------------------------------------------------------------
#define GBM 128
#define GBN 128
#define GBK 32
#define GLD (GBK + 4)   // 36 floats/row: bank = 4*row + col -> conflict-free frags

__global__ void __launch_bounds__(256) gemm_nt_tf32(const float* __restrict__ A,
                                                    const float* __restrict__ B,
                                                    float* __restrict__ C,
                                                    int M, int N, int K) {
    __shared__ float As[GBM][GLD];
    __shared__ float Bs[GBN][GLD];

    const int tid  = threadIdx.x;
    const int warp = tid >> 5, lane = tid & 31;
    const int wm   = warp >> 2;        // 0..1
    const int wn   = warp & 3;         // 0..3
    const int g    = lane >> 2;        // 0..7
    const int tg   = lane & 3;         // 0..3
    const int bm   = blockIdx.y * GBM;
    const int bn   = blockIdx.x * GBN;

    const int lrow = tid >> 3;         // 0..31
    const int lc   = (tid & 7) * 4;    // 0..28

    float acc[4][4][4];
#pragma unroll
    for (int mt = 0; mt < 4; mt++)
#pragma unroll
        for (int nt = 0; nt < 4; nt++)
#pragma unroll
            for (int i = 0; i < 4; i++) acc[mt][nt][i] = 0.f;

    for (int k0 = 0; k0 < K; k0 += GBK) {
#pragma unroll
        for (int p = 0; p < 4; p++) {
            int r = lrow + p * 32;
            float4 a4 = *(const float4*)(A + (size_t)(bm + r) * K + k0 + lc);
            float4 b4 = *(const float4*)(B + (size_t)(bn + r) * K + k0 + lc);
            *(float4*)&As[r][lc] = make_float4(f2tf(a4.x), f2tf(a4.y), f2tf(a4.z), f2tf(a4.w));
            *(float4*)&Bs[r][lc] = make_float4(f2tf(b4.x), f2tf(b4.y), f2tf(b4.z), f2tf(b4.w));
        }
        __syncthreads();

#pragma unroll
        for (int ks = 0; ks < GBK / 8; ks++) {
            const int kb = ks * 8;
            uint32_t af[4][4], bf[4][2];
#pragma unroll
            for (int mt = 0; mt < 4; mt++) {
                int r = wm * 64 + mt * 16 + g;
                af[mt][0] = __float_as_uint(As[r    ][kb + tg]);
                af[mt][1] = __float_as_uint(As[r + 8][kb + tg]);
                af[mt][2] = __float_as_uint(As[r    ][kb + tg + 4]);
                af[mt][3] = __float_as_uint(As[r + 8][kb + tg + 4]);
            }
#pragma unroll
            for (int nt = 0; nt < 4; nt++) {
                int c = wn * 32 + nt * 8 + g;
                bf[nt][0] = __float_as_uint(Bs[c][kb + tg]);
                bf[nt][1] = __float_as_uint(Bs[c][kb + tg + 4]);
            }
#pragma unroll
            for (int mt = 0; mt < 4; mt++)
#pragma unroll
                for (int nt = 0; nt < 4; nt++) mma8(acc[mt][nt], af[mt], bf[nt]);
        }
        __syncthreads();
    }

#pragma unroll
    for (int mt = 0; mt < 4; mt++)
#pragma unroll
        for (int nt = 0; nt < 4; nt++) {
            int r0 = bm + wm * 64 + mt * 16 + g;
            int c  = bn + wn * 32 + nt * 8 + 2 * tg;
            *(float2*)(C + (size_t)r0 * N + c)       = make_float2(acc[mt][nt][0], acc[mt][nt][1]);
            *(float2*)(C + (size_t)(r0 + 8) * N + c) = make_float2(acc[mt][nt][2], acc[mt][nt][3]);
        }
}

// ---------------------------------------------------------------------------
// Flash attention with tf32 mma.
// Grid (S/64, H), 256 threads = 8 warps as 4(m-rows) x 2(n-halves).
// Q fragments persistent in registers; K-tile SMEM aliased with P buffer;
// V in natural [t][d] layout (pad 72 -> conflict-free B frags).
// ---------------------------------------------------------------------------
#define BQ 64
#define BT 64
#define KLD (DK + 4)   // 68: Ks[t][dk] / Ps[q][t]
#define VLD (BT + 8)   // 72: Vs[t][d], bank = 8*tg + g -> conflict-free

__global__ void __launch_bounds__(256) attn_mma(const float* __restrict__ Qg,
                                                const float* __restrict__ Kg,
                                                const float* __restrict__ Vg,
                                                float* __restrict__ Og) {
    __shared__ float KsPs[BT][KLD];    // phase A: K[t][dk]; phase B: P[q][t]
    __shared__ float Vs[BT][VLD];      // V[t][d]
    __shared__ float smax[BQ][2], ssum[BQ][2];

    const int h   = blockIdx.y;
    const int q0  = blockIdx.x * BQ;
    const int tid = threadIdx.x;
    const int warp = tid >> 5, lane = tid & 31;
    const int wm  = warp >> 1;         // 0..3 -> q rows [wm*16, wm*16+16)
    const int wn  = warp & 1;          // 0..1 -> kv/d cols [wn*32, wn*32+32)
    const int g   = lane >> 2;         // 0..7
    const int tg  = lane & 3;          // 0..3

    const int r0 = wm * 16 + g;        // local q row (a0/a2/c0/c1)
    const int r1 = r0 + 8;             // local q row (a1/a3/c2/c3)

    // ---- Persistent Q fragments (pre-scaled by 1/sqrt(dk)) ----
    uint32_t qf[8][4];
    {
        const float* qp0 = Qg + (size_t)(q0 + r0) * DMODEL + h * DK;
        const float* qp1 = Qg + (size_t)(q0 + r1) * DMODEL + h * DK;
#pragma unroll
        for (int ks = 0; ks < 8; ks++) {
            int kc = ks * 8 + tg;
            qf[ks][0] = __float_as_uint(f2tf(qp0[kc]     * 0.125f));
            qf[ks][1] = __float_as_uint(f2tf(qp1[kc]     * 0.125f));
            qf[ks][2] = __float_as_uint(f2tf(qp0[kc + 4] * 0.125f));
            qf[ks][3] = __float_as_uint(f2tf(qp1[kc + 4] * 0.125f));
        }
    }

    float m0 = -1e30f, m1 = -1e30f, l0 = 0.f, l1 = 0.f;
    float oacc[4][4];
#pragma unroll
    for (int nt = 0; nt < 4; nt++)
#pragma unroll
        for (int i = 0; i < 4; i++) oacc[nt][i] = 0.f;

    for (int t0 = 0; t0 < S_LEN; t0 += BT) {
        __syncthreads();   // prev PV done reading Ps/Vs before overwrite

        // ---- load K tile [t][dk] (tf32) ----
#pragma unroll
        for (int p = 0; p < 4; p++) {
            int idx = p * 256 + tid;
            int r  = idx >> 4;
            int c4 = (idx & 15) * 4;
            float4 t4 = *(const float4*)(Kg + (size_t)(t0 + r) * DMODEL + h * DK + c4);
            *(float4*)&KsPs[r][c4] = make_float4(f2tf(t4.x), f2tf(t4.y), f2tf(t4.z), f2tf(t4.w));
        }
        // ---- load V tile [t][d] (tf32) ----
#pragma unroll
        for (int p = 0; p < 4; p++) {
            int idx = p * 256 + tid;
            int r  = idx >> 4;
            int c4 = (idx & 15) * 4;
            float4 t4 = *(const float4*)(Vg + (size_t)(t0 + r) * DMODEL + h * DK + c4);
            *(float4*)&Vs[r][c4] = make_float4(f2tf(t4.x), f2tf(t4.y), f2tf(t4.z), f2tf(t4.w));
        }
        __syncthreads();

        // ---- S = (Q/8) K^T : warp computes 16 x 32 ----
        float accS[4][4];
#pragma unroll
        for (int nt = 0; nt < 4; nt++)
#pragma unroll
            for (int i = 0; i < 4; i++) accS[nt][i] = 0.f;

#pragma unroll
        for (int ks = 0; ks < 8; ks++) {
            const int kb = ks * 8;
            uint32_t bf[4][2];
#pragma unroll
            for (int nt = 0; nt < 4; nt++) {
                int t = wn * 32 + nt * 8 + g;
                bf[nt][0] = __float_as_uint(KsPs[t][kb + tg]);
                bf[nt][1] = __float_as_uint(KsPs[t][kb + tg + 4]);
            }
#pragma unroll
            for (int nt = 0; nt < 4; nt++) mma8(accS[nt], qf[ks], bf[nt]);
        }

        // ---- online softmax: partial row max ----
        float mx0 = -1e30f, mx1 = -1e30f;
#pragma unroll
        for (int nt = 0; nt < 4; nt++) {
            mx0 = fmaxf(mx0, fmaxf(accS[nt][0], accS[nt][1]));
            mx1 = fmaxf(mx1, fmaxf(accS[nt][2], accS[nt][3]));
        }
        mx0 = fmaxf(mx0, __shfl_xor_sync(0xffffffffu, mx0, 1));
        mx0 = fmaxf(mx0, __shfl_xor_sync(0xffffffffu, mx0, 2));
        mx1 = fmaxf(mx1, __shfl_xor_sync(0xffffffffu, mx1, 1));
        mx1 = fmaxf(mx1, __shfl_xor_sync(0xffffffffu, mx1, 2));
        if (tg == 0) { smax[r0][wn] = mx0; smax[r1][wn] = mx1; }
        __syncthreads();   // also: all K reads done -> Ps may overwrite

        float mn0 = fmaxf(fmaxf(smax[r0][0], smax[r0][1]), m0);
        float mn1 = fmaxf(fmaxf(smax[r1][0], smax[r1][1]), m1);
        float c0 = __expf(m0 - mn0), c1 = __expf(m1 - mn1);
        m0 = mn0; m1 = mn1;

        float ps0 = 0.f, ps1 = 0.f;
#pragma unroll
        for (int nt = 0; nt < 4; nt++) {
            int c = wn * 32 + nt * 8 + 2 * tg;
            float p00 = __expf(accS[nt][0] - m0);
            float p01 = __expf(accS[nt][1] - m0);
            float p10 = __expf(accS[nt][2] - m1);
            float p11 = __expf(accS[nt][3] - m1);
            ps0 += p00 + p01; ps1 += p10 + p11;
            *(float2*)&KsPs[r0][c] = make_float2(f2tf(p00), f2tf(p01));
            *(float2*)&KsPs[r1][c] = make_float2(f2tf(p10), f2tf(p11));
        }
        ps0 += __shfl_xor_sync(0xffffffffu, ps0, 1);
        ps0 += __shfl_xor_sync(0xffffffffu, ps0, 2);
        ps1 += __shfl_xor_sync(0xffffffffu, ps1, 1);
        ps1 += __shfl_xor_sync(0xffffffffu, ps1, 2);
        if (tg == 0) { ssum[r0][wn] = ps0; ssum[r1][wn] = ps1; }
        __syncthreads();   // Ps + ssum visible

        l0 = l0 * c0 + ssum[r0][0] + ssum[r0][1];
        l1 = l1 * c1 + ssum[r1][0] + ssum[r1][1];
#pragma unroll
        for (int nt = 0; nt < 4; nt++) {
            oacc[nt][0] *= c0; oacc[nt][1] *= c0;
            oacc[nt][2] *= c1; oacc[nt][3] *= c1;
        }

        // ---- O += P V : warp computes 16 x 32 over d ----
#pragma unroll
        for (int ks = 0; ks < 8; ks++) {
            const int kb = ks * 8;
            uint32_t af[4], bf[4][2];
            af[0] = __float_as_uint(KsPs[r0][kb + tg]);
            af[1] = __float_as_uint(KsPs[r1][kb + tg]);
            af[2] = __float_as_uint(KsPs[r0][kb + tg + 4]);
            af[3] = __float_as_uint(KsPs[r1][kb + tg + 4]);
#pragma unroll
            for (int nt = 0; nt < 4; nt++) {
                int d = wn * 32 + nt * 8 + g;
                bf[nt][0] = __float_as_uint(Vs[kb + tg][d]);
                bf[nt][1] = __float_as_uint(Vs[kb + tg + 4][d]);
            }
#pragma unroll
            for (int nt = 0; nt < 4; nt++) mma8(oacc[nt], af, bf[nt]);
        }
    }

    // ---- normalize + write ----
    float inv0 = 1.f / l0, inv1 = 1.f / l1;
#pragma unroll
    for (int nt = 0; nt < 4; nt++) {
        int c = h * DK + wn * 32 + nt * 8 + 2 * tg;
        *(float2*)(Og + (size_t)(q0 + r0) * DMODEL + c) =
            make_float2(oacc[nt][0] * inv0, oacc[nt][1] * inv0);
        *(float2*)(Og + (size_t)(q0 + r1) * DMODEL + c) =
            make_float2(oacc[nt][2] * inv1, oacc[nt][3] * inv1);
    }
}

// ---------------------------------------------------------------------------
extern "C" void kernel_launch(void* const* d_in, const int* in_sizes, int n_in,
                              void* d_out, int out_size) {
    const float* x  = (const float*)d_in[0];
    const float* Wq = (const float*)d_in[1];
    const float* Wk = (const float*)d_in[2];
    const float* Wv = (const float*)d_in[3];
    const float* Wo = (const float*)d_in[4];
    float* out = (float*)d_out;

    float *q, *k, *v, *ao;
    cudaGetSymbolAddress((void**)&q,  g_q);
    cudaGetSymbolAddress((void**)&k,  g_k);
    cudaGetSymbolAddress((void**)&v,  g_v);
    cudaGetSymbolAddress((void**)&ao, g_ao);

    dim3 gg(DMODEL / GBN, S_LEN / GBM);  // (8, 32)
    gemm_nt_tf32<<<gg, 256>>>(x, Wq, q, S_LEN, DMODEL, DMODEL);
    gemm_nt_tf32<<<gg, 256>>>(x, Wk, k, S_LEN, DMODEL, DMODEL);
    gemm_nt_tf32<<<gg, 256>>>(x, Wv, v, S_LEN, DMODEL, DMODEL);

    attn_mma<<<dim3(S_LEN / BQ, NHEADS), 256>>>(q, k, v, ao);

    gemm_nt_tf32<<<gg, 256>>>(ao, Wo, out, S_LEN, DMODEL, DMODEL);
}